// round 14
// baseline (speedup 1.0000x reference)
#include <cuda_runtime.h>
#include <cuda_bf16.h>
#include <cstdint>
#include <math.h>

// Problem constants
#define BB 8
#define TT 2048
#define DD 1024
#define HH 128
#define MM (BB*TT)

// q scale includes softmax 1/sqrt(128) AND log2(e) for base-2 softmax
#define QSCALE 0.12751739641379968f

// Scratch: Q/K/V as bf16 hi/lo splits (scale folded into Q)
__device__ __nv_bfloat16 g_qh[MM*HH];
__device__ __nv_bfloat16 g_ql[MM*HH];
__device__ __nv_bfloat16 g_kh[MM*HH];
__device__ __nv_bfloat16 g_kl[MM*HH];
__device__ __nv_bfloat16 g_vh[MM*HH];
__device__ __nv_bfloat16 g_vl[MM*HH];
__device__ __nv_bfloat16 g_wh[3*HH*DD]; // W hi, transposed [w][n][k]
__device__ __nv_bfloat16 g_wl[3*HH*DD]; // W lo, transposed

// ---------------------------------------------------------------------------
// PTX helpers
// ---------------------------------------------------------------------------
__device__ __forceinline__ uint32_t smem_u32(const void* p) {
    uint32_t a;
    asm("{ .reg .u64 t; cvta.to.shared.u64 t, %1; cvt.u32.u64 %0, t; }"
        : "=r"(a) : "l"(p));
    return a;
}

__device__ __forceinline__ void ldsm_x4(uint32_t& r0, uint32_t& r1,
                                        uint32_t& r2, uint32_t& r3,
                                        uint32_t addr) {
    asm volatile("ldmatrix.sync.aligned.m8n8.x4.shared.b16 {%0,%1,%2,%3}, [%4];"
                 : "=r"(r0), "=r"(r1), "=r"(r2), "=r"(r3) : "r"(addr));
}

__device__ __forceinline__ void ldsm_x4_t(uint32_t& r0, uint32_t& r1,
                                          uint32_t& r2, uint32_t& r3,
                                          uint32_t addr) {
    asm volatile("ldmatrix.sync.aligned.m8n8.x4.trans.shared.b16 {%0,%1,%2,%3}, [%4];"
                 : "=r"(r0), "=r"(r1), "=r"(r2), "=r"(r3) : "r"(addr));
}

__device__ __forceinline__ void mma_bf16(float* c, const uint32_t* a,
                                         uint32_t b0, uint32_t b1) {
    asm volatile(
        "mma.sync.aligned.m16n8k16.row.col.f32.bf16.bf16.f32 "
        "{%0,%1,%2,%3}, {%4,%5,%6,%7}, {%8,%9}, {%0,%1,%2,%3};"
        : "+f"(c[0]), "+f"(c[1]), "+f"(c[2]), "+f"(c[3])
        : "r"(a[0]), "r"(a[1]), "r"(a[2]), "r"(a[3]), "r"(b0), "r"(b1));
}

__device__ __forceinline__ uint32_t pack_bf16x2(float a, float b) {
    __nv_bfloat162 p = __halves2bfloat162(__float2bfloat16(a), __float2bfloat16(b));
    return *(uint32_t*)&p;
}

__device__ __forceinline__ void cp_async16(uint32_t dst, const void* src) {
    asm volatile("cp.async.cg.shared.global [%0], [%1], 16;"
                 :: "r"(dst), "l"(src) : "memory");
}
__device__ __forceinline__ void cp_commit() {
    asm volatile("cp.async.commit_group;" ::: "memory");
}
template<int N>
__device__ __forceinline__ void cp_wait() {
    asm volatile("cp.async.wait_group %0;" :: "n"(N) : "memory");
}

// ---------------------------------------------------------------------------
// Kernel 0: split + transpose W -> Wh_t, Wl_t  ([w][n][k], bf16)
// ---------------------------------------------------------------------------
__global__ __launch_bounds__(256) void split_w_kernel(
    const float* __restrict__ Wq,
    const float* __restrict__ Wk,
    const float* __restrict__ Wv)
{
    int i = blockIdx.x * 256 + threadIdx.x;   // < 3*DD*HH
    int widx = i / (DD * HH);
    int rem  = i - widx * DD * HH;
    int k = rem / HH;
    int n = rem % HH;
    const float* W = (widx == 0) ? Wq : (widx == 1) ? Wk : Wv;
    float v = W[k * HH + n];
    __nv_bfloat16 h = __float2bfloat16(v);
    __nv_bfloat16 l = __float2bfloat16(v - __bfloat162float(h));
    size_t dst = (size_t)widx * HH * DD + (size_t)n * DD + k;
    g_wh[dst] = h;
    g_wl[dst] = l;
}

// ---------------------------------------------------------------------------
// Kernel 1: QKV GEMM, R5 shape (BM=128, warp m32xn64, one weight per CTA)
// with fused in-kernel X fp32 -> bf16 hi/lo split (no split_x kernel).
// Grid (128 Mtiles, 3 weights); 256 threads = 8 warps: 4(M m32) x 2(N n64).
// BK=32; static smem 4 x 128x40 bf16 = 40KB; 2 CTAs/SM.
// ---------------------------------------------------------------------------
#define GP 40

__global__ __launch_bounds__(256, 2) void qkv_mma_kernel(const float* __restrict__ x)
{
    __shared__ __align__(16) __nv_bfloat16 sAh[128 * GP];
    __shared__ __align__(16) __nv_bfloat16 sAl[128 * GP];
    __shared__ __align__(16) __nv_bfloat16 sBh[128 * GP];
    __shared__ __align__(16) __nv_bfloat16 sBl[128 * GP];

    const int tid  = threadIdx.x;
    const int wid  = tid >> 5;
    const int lane = tid & 31;
    const int m0   = blockIdx.x * 128;
    const int widx = blockIdx.y;

    const float* xp = x + (size_t)m0 * DD;
    const __nv_bfloat16* wh = g_wh + (size_t)widx * HH * DD;
    const __nv_bfloat16* wl = g_wl + (size_t)widx * HH * DD;
    __nv_bfloat16* outh = (widx == 0) ? g_qh : (widx == 1) ? g_kh : g_vh;
    __nv_bfloat16* outl = (widx == 0) ? g_ql : (widx == 1) ? g_kl : g_vl;
    const float sc = (widx == 0) ? QSCALE : 1.0f;

    const int warp_m0 = (wid & 3) * 32;    // 0,32,64,96
    const int warp_n0 = (wid >> 2) * 64;   // 0,64

    float acc[2][8][4];
    #pragma unroll
    for (int m = 0; m < 2; ++m)
        #pragma unroll
        for (int j = 0; j < 8; ++j)
            #pragma unroll
            for (int e = 0; e < 4; ++e) acc[m][j][e] = 0.f;

    // loader indexing: 128 rows, 2 half-rows of 16 elems
    const int arow = tid >> 1;             // 0..127
    const int acol = (tid & 1) * 16;       // 0 or 16

    const uint32_t aBaseH = smem_u32(sAh);
    const uint32_t aBaseL = smem_u32(sAl);
    const uint32_t bBaseH = smem_u32(sBh);
    const uint32_t bBaseL = smem_u32(sBl);
    const int frag_row = lane & 15;
    const int frag_col = (lane >> 4) * 8;

    for (int c = 0; c < 32; ++c) {
        const int k0 = c * 32;

        // --- Stage A: 16 fp32 per thread, split hi/lo, store bf16 ---
        {
            const float* src = &xp[(size_t)arow * DD + k0 + acol];
            float4 u0 = *(const float4*)&src[0];
            float4 u1 = *(const float4*)&src[4];
            float4 u2 = *(const float4*)&src[8];
            float4 u3 = *(const float4*)&src[12];
            uint32_t hh[8], ll[8];
            float f[16] = {u0.x,u0.y,u0.z,u0.w, u1.x,u1.y,u1.z,u1.w,
                           u2.x,u2.y,u2.z,u2.w, u3.x,u3.y,u3.z,u3.w};
            #pragma unroll
            for (int e = 0; e < 8; ++e) {
                float a = f[2*e], b = f[2*e+1];
                __nv_bfloat16 ha = __float2bfloat16(a);
                __nv_bfloat16 hb = __float2bfloat16(b);
                hh[e] = pack_bf16x2(a, b);
                ll[e] = pack_bf16x2(a - __bfloat162float(ha),
                                    b - __bfloat162float(hb));
            }
            uint32_t ds = (uint32_t)(arow * GP + acol);
            *(uint4*)&sAh[ds]     = *(uint4*)&hh[0];
            *(uint4*)&sAh[ds + 8] = *(uint4*)&hh[4];
            *(uint4*)&sAl[ds]     = *(uint4*)&ll[0];
            *(uint4*)&sAl[ds + 8] = *(uint4*)&ll[4];
        }
        // --- Stage B: 16 bf16 x hi/lo per thread ---
        {
            size_t gs = (size_t)arow * DD + k0 + acol;
            uint32_t ds = (uint32_t)(arow * GP + acol);
            *(uint4*)&sBh[ds]     = *(const uint4*)&wh[gs];
            *(uint4*)&sBh[ds + 8] = *(const uint4*)&wh[gs + 8];
            *(uint4*)&sBl[ds]     = *(const uint4*)&wl[gs];
            *(uint4*)&sBl[ds + 8] = *(const uint4*)&wl[gs + 8];
        }
        __syncthreads();

        #pragma unroll
        for (int s = 0; s < 2; ++s) {
            const uint32_t colOff = (uint32_t)(s * 16 + frag_col) * 2;
            uint32_t ah[2][4], al[2][4];
            #pragma unroll
            for (int m = 0; m < 2; ++m) {
                uint32_t ro = (uint32_t)(warp_m0 + m * 16 + frag_row) * (GP * 2);
                ldsm_x4(ah[m][0], ah[m][1], ah[m][2], ah[m][3], aBaseH + ro + colOff);
                ldsm_x4(al[m][0], al[m][1], al[m][2], al[m][3], aBaseL + ro + colOff);
            }
            #pragma unroll
            for (int g = 0; g < 4; ++g) {
                uint32_t ro = (uint32_t)(warp_n0 + g * 16 + frag_row) * (GP * 2);
                uint32_t b0, b1, b2, b3, c0, c1, c2, c3;
                ldsm_x4(b0, b1, b2, b3, bBaseH + ro + colOff);
                ldsm_x4(c0, c1, c2, c3, bBaseL + ro + colOff);
                #pragma unroll
                for (int m = 0; m < 2; ++m) {
                    mma_bf16(acc[m][2*g],   ah[m], b0, b2);
                    mma_bf16(acc[m][2*g+1], ah[m], b1, b3);
                    mma_bf16(acc[m][2*g],   ah[m], c0, c2);
                    mma_bf16(acc[m][2*g+1], ah[m], c1, c3);
                    mma_bf16(acc[m][2*g],   al[m], b0, b2);
                    mma_bf16(acc[m][2*g+1], al[m], b1, b3);
                }
            }
        }
        __syncthreads();
    }

    // Epilogue: split fp32 accum -> bf16 hi/lo
    #pragma unroll
    for (int m = 0; m < 2; ++m) {
        int rr = m0 + warp_m0 + m * 16 + (lane >> 2);
        #pragma unroll
        for (int j = 0; j < 8; ++j) {
            int cc = warp_n0 + j * 8 + (lane & 3) * 2;
            #pragma unroll
            for (int half = 0; half < 2; ++half) {
                float v0 = acc[m][j][half * 2]     * sc;
                float v1 = acc[m][j][half * 2 + 1] * sc;
                __nv_bfloat16 h0 = __float2bfloat16(v0);
                __nv_bfloat16 h1 = __float2bfloat16(v1);
                __nv_bfloat16 l0 = __float2bfloat16(v0 - __bfloat162float(h0));
                __nv_bfloat16 l1 = __float2bfloat16(v1 - __bfloat162float(h1));
                size_t off = (size_t)(rr + half * 8) * HH + cc;
                *(__nv_bfloat162*)&outh[off] = __halves2bfloat162(h0, h1);
                *(__nv_bfloat162*)&outl[off] = __halves2bfloat162(l0, l1);
            }
        }
    }
}

// ---------------------------------------------------------------------------
// Kernel 2: causal flash attention on tensor cores, cp.async pipelined.
// Max-free base-2 softmax (logits bounded; reference constant cancels in the
// final normalization). Unchanged from the 303.9us baseline.
// ---------------------------------------------------------------------------
#define APITCH 136
#define TILE_E (64 * APITCH)
#define ATT_SMEM_BYTES (6 * TILE_E * 2)

__global__ __launch_bounds__(128, 2) void attn_kernel(float* __restrict__ out)
{
    extern __shared__ __nv_bfloat16 smb[];
    const uint32_t smB = smem_u32(smb);
    const uint32_t KhB[2] = {smB,              smB + 2u*TILE_E*2u};
    const uint32_t KlB[2] = {smB + TILE_E*2u,  smB + 3u*TILE_E*2u};
    const uint32_t VhB = smB + 4u*TILE_E*2u;
    const uint32_t VlB = smB + 5u*TILE_E*2u;

    const int bid   = blockIdx.x;
    const int qtile = 31 - (bid >> 3);
    const int b     = bid & 7;
    const int row0  = qtile * 64;

    const __nv_bfloat16* qhp = g_qh + (size_t)b * TT * HH;
    const __nv_bfloat16* qlp = g_ql + (size_t)b * TT * HH;
    const __nv_bfloat16* khp = g_kh + (size_t)b * TT * HH;
    const __nv_bfloat16* klp = g_kl + (size_t)b * TT * HH;
    const __nv_bfloat16* vhp = g_vh + (size_t)b * TT * HH;
    const __nv_bfloat16* vlp = g_vl + (size_t)b * TT * HH;

    const int tid  = threadIdx.x;
    const int warp = tid >> 5;
    const int lane = tid & 31;
    const int frag_row = lane & 15;
    const int frag_col = (lane >> 4) * 8;

    const int crow = tid >> 4;
    const int cseg = (tid & 15) * 8;

    // ---- Stage Q, grab fragments, release buffer ----
    for (int i = tid; i < 64 * 16; i += 128) {
        int r = i >> 4, seg = (i & 15) * 8;
        *(uint4*)&smb[0*TILE_E + r * APITCH + seg] =
            *(const uint4*)&qhp[(size_t)(row0 + r) * HH + seg];
        *(uint4*)&smb[1*TILE_E + r * APITCH + seg] =
            *(const uint4*)&qlp[(size_t)(row0 + r) * HH + seg];
    }
    __syncthreads();

    uint32_t qh[8][4], ql[8][4];
    {
        uint32_t ro = (uint32_t)(warp * 16 + frag_row) * (APITCH * 2);
        #pragma unroll
        for (int g = 0; g < 8; ++g) {
            uint32_t co = (uint32_t)(g * 16 + frag_col) * 2;
            ldsm_x4(qh[g][0], qh[g][1], qh[g][2], qh[g][3], KhB[0] + ro + co);
            ldsm_x4(ql[g][0], ql[g][1], ql[g][2], ql[g][3], KlB[0] + ro + co);
        }
    }
    __syncthreads();

    // issue K(0) into buf0, then V(0)
    {
        #pragma unroll
        for (int r8 = 0; r8 < 8; ++r8) {
            int r = crow + r8 * 8;
            size_t gs = (size_t)r * HH + cseg;
            uint32_t ds = (uint32_t)(r * APITCH + cseg) * 2;
            cp_async16(KhB[0] + ds, khp + gs);
            cp_async16(KlB[0] + ds, klp + gs);
        }
        cp_commit();
        #pragma unroll
        for (int r8 = 0; r8 < 8; ++r8) {
            int r = crow + r8 * 8;
            size_t gs = (size_t)r * HH + cseg;
            uint32_t ds = (uint32_t)(r * APITCH + cseg) * 2;
            cp_async16(VhB + ds, vhp + gs);
            cp_async16(VlB + ds, vlp + gs);
        }
        cp_commit();
    }

    float o[16][4];
    #pragma unroll
    for (int j = 0; j < 16; ++j)
        #pragma unroll
        for (int e = 0; e < 4; ++e) o[j][e] = 0.f;
    float l0 = 0.f, l1 = 0.f;

    const int r0g = row0 + warp * 16 + (lane >> 2);
    const int r1g = r0g + 8;

    for (int kt = 0; kt <= qtile; ++kt) {
        const int cur = kt & 1;
        const int nxt = cur ^ 1;

        cp_wait<1>();        // K(kt) ready
        __syncthreads();

        // prefetch K(kt+1)
        {
            int knr = (kt < qtile) ? (kt + 1) * 64 : kt * 64;
            #pragma unroll
            for (int r8 = 0; r8 < 8; ++r8) {
                int r = crow + r8 * 8;
                size_t gs = (size_t)(knr + r) * HH + cseg;
                uint32_t ds = (uint32_t)(r * APITCH + cseg) * 2;
                cp_async16(KhB[nxt] + ds, khp + gs);
                cp_async16(KlB[nxt] + ds, klp + gs);
            }
            cp_commit();
        }

        // ---- S = Q K^T ----
        float s[8][4];
        #pragma unroll
        for (int j = 0; j < 8; ++j)
            #pragma unroll
            for (int e = 0; e < 4; ++e) s[j][e] = 0.f;

        #pragma unroll
        for (int g = 0; g < 8; ++g) {
            const uint32_t co = (uint32_t)(g * 16 + frag_col) * 2;
            #pragma unroll
            for (int n = 0; n < 4; ++n) {
                uint32_t ro = (uint32_t)(n * 16 + frag_row) * (APITCH * 2);
                uint32_t b0, b1, b2, b3, c0, c1, c2, c3;
                ldsm_x4(b0, b1, b2, b3, KhB[cur] + ro + co);
                ldsm_x4(c0, c1, c2, c3, KlB[cur] + ro + co);
                mma_bf16(s[2*n],   qh[g], b0, b2);
                mma_bf16(s[2*n+1], qh[g], b1, b3);
                mma_bf16(s[2*n],   qh[g], c0, c2);
                mma_bf16(s[2*n+1], qh[g], c1, c3);
                mma_bf16(s[2*n],   ql[g], b0, b2);
                mma_bf16(s[2*n+1], ql[g], b1, b3);
            }
        }

        // ---- causal mask (diagonal tile) ----
        const int kr0 = kt * 64;
        if (kt == qtile) {
            const int c0 = kr0 + (lane & 3) * 2;
            #pragma unroll
            for (int j = 0; j < 8; ++j) {
                int cg = c0 + j * 8;
                if (cg     > r0g) s[j][0] = -1e30f;
                if (cg + 1 > r0g) s[j][1] = -1e30f;
                if (cg     > r1g) s[j][2] = -1e30f;
                if (cg + 1 > r1g) s[j][3] = -1e30f;
            }
        }

        // ---- max-free softmax: p = exp2(s); accumulate per-thread l ----
        #pragma unroll
        for (int j = 0; j < 8; ++j) {
            s[j][0] = exp2f(s[j][0]);
            s[j][1] = exp2f(s[j][1]);
            s[j][2] = exp2f(s[j][2]);
            s[j][3] = exp2f(s[j][3]);
            l0 += s[j][0] + s[j][1];
            l1 += s[j][2] + s[j][3];
        }

        cp_wait<1>();        // V(kt) ready
        __syncthreads();

        // ---- O += P V ----
        #pragma unroll
        for (int g = 0; g < 4; ++g) {
            uint32_t pah[4], pal[4];
            {
                float a0 = s[2*g][0],   a1 = s[2*g][1];
                float a2 = s[2*g][2],   a3 = s[2*g][3];
                float a4 = s[2*g+1][0], a5 = s[2*g+1][1];
                float a6 = s[2*g+1][2], a7 = s[2*g+1][3];
                pah[0] = pack_bf16x2(a0, a1);
                pah[1] = pack_bf16x2(a2, a3);
                pah[2] = pack_bf16x2(a4, a5);
                pah[3] = pack_bf16x2(a6, a7);
                __nv_bfloat162 h;
                h = *(__nv_bfloat162*)&pah[0];
                pal[0] = pack_bf16x2(a0 - __bfloat162float(h.x), a1 - __bfloat162float(h.y));
                h = *(__nv_bfloat162*)&pah[1];
                pal[1] = pack_bf16x2(a2 - __bfloat162float(h.x), a3 - __bfloat162float(h.y));
                h = *(__nv_bfloat162*)&pah[2];
                pal[2] = pack_bf16x2(a4 - __bfloat162float(h.x), a5 - __bfloat162float(h.y));
                h = *(__nv_bfloat162*)&pah[3];
                pal[3] = pack_bf16x2(a6 - __bfloat162float(h.x), a7 - __bfloat162float(h.y));
            }
            const uint32_t ro = (uint32_t)(g * 16 + frag_row) * (APITCH * 2);
            #pragma unroll
            for (int h2 = 0; h2 < 8; ++h2) {
                uint32_t co = (uint32_t)(h2 * 16 + frag_col) * 2;
                uint32_t b0, b1, b2, b3, c0, c1, c2, c3;
                ldsm_x4_t(b0, b1, b2, b3, VhB + ro + co);
                ldsm_x4_t(c0, c1, c2, c3, VlB + ro + co);
                mma_bf16(o[2*h2],   pah, b0, b1);
                mma_bf16(o[2*h2+1], pah, b2, b3);
                mma_bf16(o[2*h2],   pah, c0, c1);
                mma_bf16(o[2*h2+1], pah, c2, c3);
                mma_bf16(o[2*h2],   pal, b0, b1);
                mma_bf16(o[2*h2+1], pal, b2, b3);
            }
        }

        __syncthreads();

        // prefetch V(kt+1)
        {
            int vnr = (kt < qtile) ? (kt + 1) * 64 : kt * 64;
            #pragma unroll
            for (int r8 = 0; r8 < 8; ++r8) {
                int r = crow + r8 * 8;
                size_t gs = (size_t)(vnr + r) * HH + cseg;
                uint32_t ds = (uint32_t)(r * APITCH + cseg) * 2;
                cp_async16(VhB + ds, vhp + gs);
                cp_async16(VlB + ds, vlp + gs);
            }
            cp_commit();
        }
    }

    cp_wait<0>();

    // ---- Epilogue: reduce l across the quad, normalize, store ----
    l0 += __shfl_xor_sync(0xffffffffu, l0, 1);
    l0 += __shfl_xor_sync(0xffffffffu, l0, 2);
    l1 += __shfl_xor_sync(0xffffffffu, l1, 1);
    l1 += __shfl_xor_sync(0xffffffffu, l1, 2);
    const float inv0 = 1.0f / l0;
    const float inv1 = 1.0f / l1;
    float* op = out + (size_t)b * TT * HH;
    #pragma unroll
    for (int j = 0; j < 16; ++j) {
        int cc = j * 8 + (lane & 3) * 2;
        *(float2*)&op[(size_t)r0g * HH + cc] = make_float2(o[j][0] * inv0, o[j][1] * inv0);
        *(float2*)&op[(size_t)r1g * HH + cc] = make_float2(o[j][2] * inv1, o[j][3] * inv1);
    }
}

// ---------------------------------------------------------------------------
extern "C" void kernel_launch(void* const* d_in, const int* in_sizes, int n_in,
                              void* d_out, int out_size)
{
    const float* x  = (const float*)d_in[0];
    const float* Wq = (const float*)d_in[1];
    const float* Wk = (const float*)d_in[2];
    const float* Wv = (const float*)d_in[3];
    float* out = (float*)d_out;

    split_w_kernel<<<3 * DD * HH / 256, 256>>>(Wq, Wk, Wv);

    dim3 gm(MM / 128, 3);
    qkv_mma_kernel<<<gm, 256>>>(x);

    cudaFuncSetAttribute(attn_kernel,
                         cudaFuncAttributeMaxDynamicSharedMemorySize, ATT_SMEM_BYTES);
    attn_kernel<<<BB * (TT / 64), 128, ATT_SMEM_BYTES>>>(out);
}